// round 3
// baseline (speedup 1.0000x reference)
#include <cuda_runtime.h>
#include <cuda_bf16.h>

#define NN 100000
#define NE 1600000
#define FIN 128
#define DH 32        // D*H
#define GH 64
#define HH 16
#define NOUT 10
#define NBLK 391     // (NN+255)/256

// ---------------- scratch (device globals; no allocation) ----------------
__device__ __align__(16) float g_x0[NN * DH];
__device__ __align__(16) float g_x1[NN * DH];
__device__ __align__(16) float g_m0[NN * GH];
__device__ __align__(16) float g_m1[NN * GH];
__device__ __align__(16) float4 g_node[NN];     // (cos, sin, rdeg, 0)
__device__ float g_rdeg[NN];
__device__ int g_cnt[NN];
__device__ int g_rowptr[NN + 1];
__device__ int g_cursor[NN];
__device__ int g_bsum[NBLK];
__device__ int g_bsumx[NBLK];
__device__ int g_src[NE];
__device__ int g_dst[NE];
__device__ int g_csr_src[NE];
__device__ int g_idx64;

// ---------------- helpers ----------------
__device__ __forceinline__ float gelu_f(float v) {
    const float c = 0.7978845608028654f;
    float t = tanhf(c * (v + 0.044715f * v * v * v));
    return 0.5f * v * (1.0f + t);
}

// ---------------- graph prep ----------------
__global__ void k_probe(const unsigned int* __restrict__ w) {
    if (threadIdx.x == 0) {
        int is64 = 1;
        for (int i = 0; i < 256; i++)
            if (w[2 * i + 1] != 0u) { is64 = 0; break; }
        g_idx64 = is64;
    }
}

__global__ void k_init() {
    int i = blockIdx.x * blockDim.x + threadIdx.x;
    if (i < NN) g_cnt[i] = 0;
}

__global__ void k_prep(const void* __restrict__ ei) {
    int e = blockIdx.x * blockDim.x + threadIdx.x;
    if (e >= NE) return;
    int s, d;
    if (g_idx64) {
        const long long* p = (const long long*)ei;
        s = (int)p[e]; d = (int)p[NE + e];
    } else {
        const int* p = (const int*)ei;
        s = p[e]; d = p[NE + e];
    }
    s = min(max(s, 0), NN - 1);
    d = min(max(d, 0), NN - 1);
    g_src[e] = s;
    g_dst[e] = d;
    atomicAdd(&g_cnt[d], 1);
}

__global__ void k_scan1() {
    __shared__ int sm[256];
    int t = threadIdx.x;
    int i = blockIdx.x * 256 + t;
    int v = (i < NN) ? g_cnt[i] : 0;
    sm[t] = v;
    __syncthreads();
    for (int off = 1; off < 256; off <<= 1) {
        int x = (t >= off) ? sm[t - off] : 0;
        __syncthreads();
        sm[t] += x;
        __syncthreads();
    }
    if (i < NN) g_rowptr[i] = sm[t] - v;    // block-local exclusive
    if (t == 255) g_bsum[blockIdx.x] = sm[255];
}

__global__ void k_scan2() {
    __shared__ int sm[512];
    int t = threadIdx.x;
    int v = (t < NBLK) ? g_bsum[t] : 0;
    sm[t] = v;
    __syncthreads();
    for (int off = 1; off < 512; off <<= 1) {
        int x = (t >= off) ? sm[t - off] : 0;
        __syncthreads();
        sm[t] += x;
        __syncthreads();
    }
    if (t < NBLK) g_bsumx[t] = sm[t] - v;   // exclusive block offsets
}

__global__ void k_scan3() {
    int i = blockIdx.x * blockDim.x + threadIdx.x;
    if (i < NN) {
        int rp = g_rowptr[i] + g_bsumx[i >> 8];
        g_rowptr[i] = rp;
        g_cursor[i] = rp;
        g_rdeg[i] = rsqrtf((float)g_cnt[i] + 1.0f);
    }
    if (i == 0) g_rowptr[NN] = NE;
}

__global__ void k_place() {
    int e = blockIdx.x * blockDim.x + threadIdx.x;
    if (e >= NE) return;
    int d = g_dst[e];
    int pos = atomicAdd(&g_cursor[d], 1);
    g_csr_src[pos] = g_src[e];
}

// ---------------- embed: h = x@W_in+b ; m0 = gelu(h@emb1_W+b). 32 nodes/block ----------------
__global__ __launch_bounds__(256) void k_embed(
    const float* __restrict__ x, const float* __restrict__ W_in,
    const float* __restrict__ b_in, const float* __restrict__ W2,
    const float* __restrict__ b2)
{
    __shared__ float sx[32][132];
    __shared__ float sW1[FIN * DH];
    __shared__ float sW2[DH * GH];
    __shared__ float sh[32][33];
    int tid = threadIdx.x;
    int base = blockIdx.x * 32;

    for (int i = tid; i < FIN * DH; i += 256) sW1[i] = W_in[i];
    for (int i = tid; i < DH * GH; i += 256) sW2[i] = W2[i];
    {
        int nl = tid >> 3;
        int nc = min(base + nl, NN - 1);
        int c0 = (tid & 7) * 16;
        const float4* xr = (const float4*)(x + (size_t)nc * FIN);
        float4* sxr = (float4*)&sx[nl][c0];
        #pragma unroll
        for (int j = 0; j < 4; j++) sxr[j] = xr[(tid & 7) * 4 + j];
    }
    __syncthreads();

    int ty = tid >> 3;            // node 0..31
    int tx = tid & 7;             // output group (4 outs)
    int n = base + ty;
    float4 acc = make_float4(0.f, 0.f, 0.f, 0.f);
    #pragma unroll 4
    for (int k = 0; k < FIN; k++) {
        float xv = sx[ty][k];
        float4 wv = *(const float4*)&sW1[k * DH + 4 * tx];
        acc.x += xv * wv.x; acc.y += xv * wv.y;
        acc.z += xv * wv.z; acc.w += xv * wv.w;
    }
    {
        float4 bv = *(const float4*)&b_in[4 * tx];
        acc.x += bv.x; acc.y += bv.y; acc.z += bv.z; acc.w += bv.w;
        if (n < NN) *(float4*)&g_x0[n * DH + 4 * tx] = acc;
        sh[ty][4 * tx + 0] = acc.x; sh[ty][4 * tx + 1] = acc.y;
        sh[ty][4 * tx + 2] = acc.z; sh[ty][4 * tx + 3] = acc.w;
    }
    __syncthreads();

    float a2[8] = {0.f, 0.f, 0.f, 0.f, 0.f, 0.f, 0.f, 0.f};
    #pragma unroll 4
    for (int q = 0; q < DH; q++) {
        float hv = sh[ty][q];
        float4 w0 = *(const float4*)&sW2[q * GH + 8 * tx];
        float4 w1 = *(const float4*)&sW2[q * GH + 8 * tx + 4];
        a2[0] += hv * w0.x; a2[1] += hv * w0.y; a2[2] += hv * w0.z; a2[3] += hv * w0.w;
        a2[4] += hv * w1.x; a2[5] += hv * w1.y; a2[6] += hv * w1.z; a2[7] += hv * w1.w;
    }
    if (n < NN) {
        float4 b0 = *(const float4*)&b2[8 * tx];
        float4 b1 = *(const float4*)&b2[8 * tx + 4];
        float4 o0, o1;
        o0.x = gelu_f(a2[0] + b0.x); o0.y = gelu_f(a2[1] + b0.y);
        o0.z = gelu_f(a2[2] + b0.z); o0.w = gelu_f(a2[3] + b0.w);
        o1.x = gelu_f(a2[4] + b1.x); o1.y = gelu_f(a2[5] + b1.y);
        o1.z = gelu_f(a2[6] + b1.z); o1.w = gelu_f(a2[7] + b1.w);
        *(float4*)&g_m0[n * GH + 8 * tx] = o0;
        *(float4*)&g_m0[n * GH + 8 * tx + 4] = o1;
    }
}

// ---------------- SumGNN: gather + matmul fused. 32 nodes/block ----------------
__global__ __launch_bounds__(256) void k_sumgnn(
    const float* __restrict__ min_, float* __restrict__ mout,
    const float* __restrict__ Ws, const float* __restrict__ Wn)
{
    __shared__ float sWs[GH * GH];
    __shared__ float sWn[GH * GH];
    __shared__ float sm[32][66];
    __shared__ float sa[32][66];
    int tid = threadIdx.x;
    int base = blockIdx.x * 32;
    for (int i = tid; i < GH * GH; i += 256) { sWs[i] = Ws[i]; sWn[i] = Wn[i]; }

    int w = tid >> 5, l = tid & 31;
    #pragma unroll
    for (int j = 0; j < 4; j++) {
        int nl = 4 * w + j;
        int n = base + nl;
        float2 acc = make_float2(0.f, 0.f);
        float2 acc2 = make_float2(0.f, 0.f);
        float2 mv = make_float2(0.f, 0.f);
        if (n < NN) {
            int rs = g_rowptr[n], re = g_rowptr[n + 1];
            int i = rs;
            for (; i + 1 < re; i += 2) {
                int s0 = g_csr_src[i], s1 = g_csr_src[i + 1];
                float2 v0 = *(const float2*)&min_[s0 * GH + 2 * l];
                float2 v1 = *(const float2*)&min_[s1 * GH + 2 * l];
                acc.x += v0.x; acc.y += v0.y;
                acc2.x += v1.x; acc2.y += v1.y;
            }
            if (i < re) {
                int s0 = g_csr_src[i];
                float2 v0 = *(const float2*)&min_[s0 * GH + 2 * l];
                acc.x += v0.x; acc.y += v0.y;
            }
            acc.x += acc2.x; acc.y += acc2.y;
            mv = *(const float2*)&min_[n * GH + 2 * l];
        }
        sm[nl][2 * l] = mv.x; sm[nl][2 * l + 1] = mv.y;
        sa[nl][2 * l] = acc.x; sa[nl][2 * l + 1] = acc.y;
    }
    __syncthreads();

    int nt = tid >> 3;           // node 0..31
    int ob = 8 * (tid & 7);      // output base (8 outs)
    float a[8] = {0.f, 0.f, 0.f, 0.f, 0.f, 0.f, 0.f, 0.f};
    #pragma unroll 2
    for (int q = 0; q < GH; q++) {
        float mv = sm[nt][q], av = sa[nt][q];
        float4 ws0 = *(const float4*)&sWs[q * GH + ob];
        float4 ws1 = *(const float4*)&sWs[q * GH + ob + 4];
        float4 wn0 = *(const float4*)&sWn[q * GH + ob];
        float4 wn1 = *(const float4*)&sWn[q * GH + ob + 4];
        a[0] += mv * ws0.x + av * wn0.x; a[1] += mv * ws0.y + av * wn0.y;
        a[2] += mv * ws0.z + av * wn0.z; a[3] += mv * ws0.w + av * wn0.w;
        a[4] += mv * ws1.x + av * wn1.x; a[5] += mv * ws1.y + av * wn1.y;
        a[6] += mv * ws1.z + av * wn1.z; a[7] += mv * ws1.w + av * wn1.w;
    }
    int n = base + nt;
    if (n < NN) {
        float4 o0, o1;
        o0.x = gelu_f(a[0]); o0.y = gelu_f(a[1]); o0.z = gelu_f(a[2]); o0.w = gelu_f(a[3]);
        o1.x = gelu_f(a[4]); o1.y = gelu_f(a[5]); o1.z = gelu_f(a[6]); o1.w = gelu_f(a[7]);
        *(float4*)&mout[n * GH + ob] = o0;
        *(float4*)&mout[n * GH + ob + 4] = o1;
    }
}

// ---------------- theta -> per-node (cos, sin, rdeg) ----------------
__global__ __launch_bounds__(256) void k_theta(
    const float* __restrict__ w2, const float* __restrict__ b2)
{
    int warp = threadIdx.x >> 5;
    int lane = threadIdx.x & 31;
    int n = blockIdx.x * 8 + warp;
    if (n >= NN) return;
    float acc = g_m0[n * GH + lane] * w2[lane] + g_m0[n * GH + 32 + lane] * w2[32 + lane];
    #pragma unroll
    for (int off = 16; off > 0; off >>= 1)
        acc += __shfl_xor_sync(0xFFFFFFFFu, acc, off);
    if (lane == 0) {
        float t = tanhf(acc + b2[0]);
        float ang = t * 6.283185307179586f;
        float s, c;
        sincosf(ang, &s, &c);
        g_node[n] = make_float4(c, s, g_rdeg[n], 0.f);
    }
}

// ---------------- diffusion: gather+rotate + update fused. 16 nodes/block ----------------
__global__ __launch_bounds__(256) void k_diff(
    const float* __restrict__ xin, float* __restrict__ xout,
    const float* __restrict__ W)
{
    __shared__ float sW[HH * HH];
    __shared__ float sxs[16][33];
    __shared__ float sag[16][33];
    int tid = threadIdx.x;
    int base = blockIdx.x * 16;
    if (tid < HH * HH) sW[tid] = W[tid];

    int w = tid >> 5, l = tid & 31;
    float sgn = (l < 16) ? -1.0f : 1.0f;
    #pragma unroll
    for (int j = 0; j < 2; j++) {
        int nl = 2 * w + j;
        int n = base + nl;
        float acc = 0.f, own = 0.f;
        if (n < NN) {
            float4 nf = g_node[n];
            int rs = g_rowptr[n], re = g_rowptr[n + 1];
            #pragma unroll 2
            for (int i = rs; i < re; i++) {
                int s = g_csr_src[i];
                float xv = xin[s * DH + l];
                float4 ns = g_node[s];
                float nrm = nf.z * ns.z;
                float a = (nf.x * ns.x + nf.y * ns.y) * nrm;
                float b = (nf.x * ns.y - nf.y * ns.x) * nrm;
                float other = __shfl_xor_sync(0xFFFFFFFFu, xv, 16);
                acc = fmaf(a, xv, acc);
                acc = fmaf(sgn * b, other, acc);
            }
            own = xin[n * DH + l];
        }
        sag[nl][l] = acc;
        sxs[nl][l] = own;
    }
    __syncthreads();

    #pragma unroll
    for (int r = 0; r < 2; r++) {
        int nl = (tid >> 5) + 8 * r;
        int c = tid & 31;
        int dd = c >> 4, k = c & 15;
        float acc = 0.f;
        #pragma unroll
        for (int h = 0; h < HH; h++) {
            float lx = sxs[nl][dd * HH + h] - sag[nl][dd * HH + h];
            acc = fmaf(lx, sW[h * HH + k], acc);
        }
        int n = base + nl;
        if (n < NN) xout[n * DH + c] = sxs[nl][c] - gelu_f(acc);
    }
}

// ---------------- output ----------------
__global__ __launch_bounds__(256) void k_out(
    const float* __restrict__ W_out, const float* __restrict__ b_out,
    float* __restrict__ out)
{
    int gid = blockIdx.x * blockDim.x + threadIdx.x;
    if (gid >= NN * NOUT) return;
    int n = gid / NOUT, o = gid - n * NOUT;
    float acc = b_out[o];
    #pragma unroll 8
    for (int i = 0; i < DH; i++) acc += g_x0[n * DH + i] * W_out[i * NOUT + o];
    out[gid] = acc;
}

__global__ void k_noop() {}

// device-buffer selector kernels can't be used host-side; use explicit wrappers:
__global__ __launch_bounds__(256) void k_sumgnn_01(const float* Ws, const float* Wn);
__global__ __launch_bounds__(256) void k_sumgnn_10(const float* Ws, const float* Wn);

// Wrappers that bind the double buffers on device (pointers to __device__ arrays
// are valid inside kernels; simplest is thin forwarding kernels):
__global__ __launch_bounds__(256) void k_sumgnn_a(const float* __restrict__ Ws, const float* __restrict__ Wn);
__global__ __launch_bounds__(256) void k_sumgnn_b(const float* __restrict__ Ws, const float* __restrict__ Wn);

// (Implemented via templates below to avoid code duplication.)

template <int SRC>
__global__ __launch_bounds__(256) void k_sumgnn_t(const float* __restrict__ Ws,
                                                  const float* __restrict__ Wn)
{
    const float* min_ = SRC ? g_m1 : g_m0;
    float* mout       = SRC ? g_m0 : g_m1;
    __shared__ float sWs[GH * GH];
    __shared__ float sWn[GH * GH];
    __shared__ float sm[32][66];
    __shared__ float sa[32][66];
    int tid = threadIdx.x;
    int base = blockIdx.x * 32;
    for (int i = tid; i < GH * GH; i += 256) { sWs[i] = Ws[i]; sWn[i] = Wn[i]; }

    int w = tid >> 5, l = tid & 31;
    #pragma unroll
    for (int j = 0; j < 4; j++) {
        int nl = 4 * w + j;
        int n = base + nl;
        float2 acc = make_float2(0.f, 0.f);
        float2 acc2 = make_float2(0.f, 0.f);
        float2 mv = make_float2(0.f, 0.f);
        if (n < NN) {
            int rs = g_rowptr[n], re = g_rowptr[n + 1];
            int i = rs;
            for (; i + 1 < re; i += 2) {
                int s0 = g_csr_src[i], s1 = g_csr_src[i + 1];
                float2 v0 = *(const float2*)&min_[s0 * GH + 2 * l];
                float2 v1 = *(const float2*)&min_[s1 * GH + 2 * l];
                acc.x += v0.x; acc.y += v0.y;
                acc2.x += v1.x; acc2.y += v1.y;
            }
            if (i < re) {
                int s0 = g_csr_src[i];
                float2 v0 = *(const float2*)&min_[s0 * GH + 2 * l];
                acc.x += v0.x; acc.y += v0.y;
            }
            acc.x += acc2.x; acc.y += acc2.y;
            mv = *(const float2*)&min_[n * GH + 2 * l];
        }
        sm[nl][2 * l] = mv.x; sm[nl][2 * l + 1] = mv.y;
        sa[nl][2 * l] = acc.x; sa[nl][2 * l + 1] = acc.y;
    }
    __syncthreads();

    int nt = tid >> 3;
    int ob = 8 * (tid & 7);
    float a[8] = {0.f, 0.f, 0.f, 0.f, 0.f, 0.f, 0.f, 0.f};
    #pragma unroll 2
    for (int q = 0; q < GH; q++) {
        float mv = sm[nt][q], av = sa[nt][q];
        float4 ws0 = *(const float4*)&sWs[q * GH + ob];
        float4 ws1 = *(const float4*)&sWs[q * GH + ob + 4];
        float4 wn0 = *(const float4*)&sWn[q * GH + ob];
        float4 wn1 = *(const float4*)&sWn[q * GH + ob + 4];
        a[0] += mv * ws0.x + av * wn0.x; a[1] += mv * ws0.y + av * wn0.y;
        a[2] += mv * ws0.z + av * wn0.z; a[3] += mv * ws0.w + av * wn0.w;
        a[4] += mv * ws1.x + av * wn1.x; a[5] += mv * ws1.y + av * wn1.y;
        a[6] += mv * ws1.z + av * wn1.z; a[7] += mv * ws1.w + av * wn1.w;
    }
    int n = base + nt;
    if (n < NN) {
        float4 o0, o1;
        o0.x = gelu_f(a[0]); o0.y = gelu_f(a[1]); o0.z = gelu_f(a[2]); o0.w = gelu_f(a[3]);
        o1.x = gelu_f(a[4]); o1.y = gelu_f(a[5]); o1.z = gelu_f(a[6]); o1.w = gelu_f(a[7]);
        *(float4*)&mout[n * GH + ob] = o0;
        *(float4*)&mout[n * GH + ob + 4] = o1;
    }
}

template <int SRC>
__global__ __launch_bounds__(256) void k_diff_t(const float* __restrict__ W)
{
    const float* xin = SRC ? g_x1 : g_x0;
    float* xout      = SRC ? g_x0 : g_x1;
    __shared__ float sW[HH * HH];
    __shared__ float sxs[16][33];
    __shared__ float sag[16][33];
    int tid = threadIdx.x;
    int base = blockIdx.x * 16;
    if (tid < HH * HH) sW[tid] = W[tid];

    int w = tid >> 5, l = tid & 31;
    float sgn = (l < 16) ? -1.0f : 1.0f;
    #pragma unroll
    for (int j = 0; j < 2; j++) {
        int nl = 2 * w + j;
        int n = base + nl;
        float acc = 0.f, own = 0.f;
        if (n < NN) {
            float4 nf = g_node[n];
            int rs = g_rowptr[n], re = g_rowptr[n + 1];
            #pragma unroll 2
            for (int i = rs; i < re; i++) {
                int s = g_csr_src[i];
                float xv = xin[s * DH + l];
                float4 ns = g_node[s];
                float nrm = nf.z * ns.z;
                float a = (nf.x * ns.x + nf.y * ns.y) * nrm;
                float b = (nf.x * ns.y - nf.y * ns.x) * nrm;
                float other = __shfl_xor_sync(0xFFFFFFFFu, xv, 16);
                acc = fmaf(a, xv, acc);
                acc = fmaf(sgn * b, other, acc);
            }
            own = xin[n * DH + l];
        }
        sag[nl][l] = acc;
        sxs[nl][l] = own;
    }
    __syncthreads();

    #pragma unroll
    for (int r = 0; r < 2; r++) {
        int nl = (tid >> 5) + 8 * r;
        int c = tid & 31;
        int dd = c >> 4, k = c & 15;
        float acc = 0.f;
        #pragma unroll
        for (int h = 0; h < HH; h++) {
            float lx = sxs[nl][dd * HH + h] - sag[nl][dd * HH + h];
            acc = fmaf(lx, sW[h * HH + k], acc);
        }
        int n = base + nl;
        if (n < NN) xout[n * DH + c] = sxs[nl][c] - gelu_f(acc);
    }
}

// ---------------- launch ----------------
extern "C" void kernel_launch(void* const* d_in, const int* in_sizes, int n_in,
                              void* d_out, int out_size) {
    int i_x = 0, i_ei = 1;
    for (int i = 0; i < n_in; i++) {
        if (in_sizes[i] == NN * FIN) i_x = i;
        if (in_sizes[i] == 2 * NE)   i_ei = i;
    }
    const float* x  = (const float*)d_in[i_x];
    const void*  ei = d_in[i_ei];
    const float* W_in   = (const float*)d_in[2];
    const float* b_in   = (const float*)d_in[3];
    const float* emb1_W = (const float*)d_in[4];
    const float* emb1_b = (const float*)d_in[5];
    const float* Ws1    = (const float*)d_in[6];
    const float* Wn1    = (const float*)d_in[7];
    const float* Ws2    = (const float*)d_in[8];
    const float* Wn2    = (const float*)d_in[9];
    const float* emb2_W = (const float*)d_in[10];
    const float* emb2_b = (const float*)d_in[11];
    const float* W_diff = (const float*)d_in[12];
    const float* W_out  = (const float*)d_in[13];
    const float* b_out  = (const float*)d_in[14];
    float* out = (float*)d_out;

    k_probe<<<1, 32>>>((const unsigned int*)ei);
    k_init<<<(NN + 255) / 256, 256>>>();
    k_prep<<<(NE + 255) / 256, 256>>>(ei);
    k_scan1<<<NBLK, 256>>>();
    k_scan2<<<1, 512>>>();
    k_scan3<<<NBLK, 256>>>();
    k_place<<<(NE + 255) / 256, 256>>>();

    k_embed<<<(NN + 31) / 32, 256>>>(x, W_in, b_in, emb1_W, emb1_b);

    k_sumgnn_t<0><<<(NN + 31) / 32, 256>>>(Ws1, Wn1);  // m0 -> m1
    k_sumgnn_t<1><<<(NN + 31) / 32, 256>>>(Ws2, Wn2);  // m1 -> m0

    k_theta<<<(NN + 7) / 8, 256>>>(emb2_W, emb2_b);

    k_diff_t<0><<<(NN + 15) / 16, 256>>>(W_diff);            // x0 -> x1
    k_diff_t<1><<<(NN + 15) / 16, 256>>>(W_diff + HH * HH);  // x1 -> x0

    k_out<<<(NN * NOUT + 255) / 256, 256>>>(W_out, b_out, out);
}